// round 10
// baseline (speedup 1.0000x reference)
#include <cuda_runtime.h>
#include <cuda_fp16.h>
#include <cstdint>

#define N_NODES    100000
#define EMB_DIM    128
#define BATCH      16384
#define NUM_SAMPLE 25

// fp16 shadow table: 100000 x 128 halfs = 25.6 MB (static device global)
__device__ __half g_emb_h[(size_t)N_NODES * EMB_DIM];

// ---------------- pass 1: fp32 table -> fp16 shadow (R5-proven) ----------------
__global__ __launch_bounds__(256) void convert_kernel(const float4* __restrict__ emb)
{
    const int n = N_NODES * EMB_DIM / 8;   // 1,600,000 uint4-of-halfs
    int i = blockIdx.x * blockDim.x + threadIdx.x;
    if (i >= n) return;

    float4 a = __ldg(&emb[2 * i]);
    float4 b = __ldg(&emb[2 * i + 1]);

    __half2 h0 = __float22half2_rn(make_float2(a.x, a.y));
    __half2 h1 = __float22half2_rn(make_float2(a.z, a.w));
    __half2 h2 = __float22half2_rn(make_float2(b.x, b.y));
    __half2 h3 = __float22half2_rn(make_float2(b.z, b.w));

    uint4 o;
    o.x = *reinterpret_cast<unsigned int*>(&h0);
    o.y = *reinterpret_cast<unsigned int*>(&h1);
    o.z = *reinterpret_cast<unsigned int*>(&h2);
    o.w = *reinterpret_cast<unsigned int*>(&h3);
    reinterpret_cast<uint4*>(g_emb_h)[i] = o;
}

// ---------------- pass 2: gather-mean, 1 warp per row, 2 samples/iter ----------------
// Proven launch shape: 2048 blocks x 256 threads = 16384 warps (one per row).
// Per iteration the warp gathers TWO sample rows: lanes 0-15 cover sample 2s,
// lanes 16-31 cover sample 2s+1; each lane loads one uint4 = 8 halfs (full
// LDG.128 width). Butterfly(16) at the end merges even/odd-sample partials.
#define GATHER_THREADS 256
#define GATHER_BLOCKS  (BATCH / (GATHER_THREADS / 32))   // 2048

__global__ __launch_bounds__(GATHER_THREADS) void gather_kernel(
    const int* __restrict__ neigh,   // [BATCH, NUM_SAMPLE] int32
    float4* __restrict__ out)        // [BATCH, 32] as float4
{
    const int warp_id = (blockIdx.x * GATHER_THREADS + threadIdx.x) >> 5;
    const int lane    = threadIdx.x & 31;
    const int sub     = lane & 15;    // dim-chunk within the row: dims [8*sub, 8*sub+8)
    const int half_hi = lane >> 4;    // 0 -> even samples, 1 -> odd samples

    // Lane l (<25) holds sample l's neighbor index for this row.
    const int* nb = neigh + warp_id * NUM_SAMPLE;
    int my_idx = (lane < NUM_SAMPLE) ? nb[lane] : 0;

    const uint4* embh = reinterpret_cast<const uint4*>(g_emb_h);  // 16 uint4 per row

    float acc[8] = {0.f, 0.f, 0.f, 0.f, 0.f, 0.f, 0.f, 0.f};

    #pragma unroll
    for (int s = 0; s < 12; ++s) {
        int id0 = __shfl_sync(0xffffffffu, my_idx, 2 * s);
        int id1 = __shfl_sync(0xffffffffu, my_idx, 2 * s + 1);
        int id  = half_hi ? id1 : id0;

        uint4 u = __ldg(&embh[(unsigned)id * 16u + sub]);

        float2 f0 = __half22float2(*reinterpret_cast<__half2*>(&u.x));
        float2 f1 = __half22float2(*reinterpret_cast<__half2*>(&u.y));
        float2 f2 = __half22float2(*reinterpret_cast<__half2*>(&u.z));
        float2 f3 = __half22float2(*reinterpret_cast<__half2*>(&u.w));

        acc[0] += f0.x; acc[1] += f0.y;
        acc[2] += f1.x; acc[3] += f1.y;
        acc[4] += f2.x; acc[5] += f2.y;
        acc[6] += f3.x; acc[7] += f3.y;
    }

    // Sample 24: lo half only.
    {
        int id24 = __shfl_sync(0xffffffffu, my_idx, 24);
        if (!half_hi) {
            uint4 u = __ldg(&embh[(unsigned)id24 * 16u + sub]);
            float2 f0 = __half22float2(*reinterpret_cast<__half2*>(&u.x));
            float2 f1 = __half22float2(*reinterpret_cast<__half2*>(&u.y));
            float2 f2 = __half22float2(*reinterpret_cast<__half2*>(&u.z));
            float2 f3 = __half22float2(*reinterpret_cast<__half2*>(&u.w));
            acc[0] += f0.x; acc[1] += f0.y;
            acc[2] += f1.x; acc[3] += f1.y;
            acc[4] += f2.x; acc[5] += f2.y;
            acc[6] += f3.x; acc[7] += f3.y;
        }
    }

    // Merge even-sample (lo half) and odd-sample (hi half) partials.
    #pragma unroll
    for (int k = 0; k < 8; ++k)
        acc[k] += __shfl_xor_sync(0xffffffffu, acc[k], 16);

    const float inv = 1.0f / (float)NUM_SAMPLE;
    #pragma unroll
    for (int k = 0; k < 8; ++k) acc[k] *= inv;

    // Lane sub owns float4s {2*sub, 2*sub+1}; lo half writes the first,
    // hi half the second -> 32 lanes store 32 distinct float4s (512 B coalesced).
    float4 v = half_hi ? make_float4(acc[4], acc[5], acc[6], acc[7])
                       : make_float4(acc[0], acc[1], acc[2], acc[3]);
    out[(unsigned)warp_id * 32u + 2u * sub + (unsigned)half_hi] = v;
}

extern "C" void kernel_launch(void* const* d_in, const int* in_sizes, int n_in,
                              void* d_out, int out_size)
{
    const float4* emb   = (const float4*)d_in[0];
    const int*    neigh = (const int*)d_in[1];
    float4*       out   = (float4*)d_out;

    const int n_conv = N_NODES * EMB_DIM / 8;
    convert_kernel<<<(n_conv + 255) / 256, 256>>>(emb);

    gather_kernel<<<GATHER_BLOCKS, GATHER_THREADS>>>(neigh, out);
}

// round 11
// speedup vs baseline: 1.2648x; 1.2648x over previous
#include <cuda_runtime.h>
#include <cstdint>

#define N_NODES    100000
#define EMB_DIM    128
#define BATCH      16384
#define NUM_SAMPLE 25

#define VEC_PER_ROW (EMB_DIM / 4)   // 32 float4 per row

// Proven shape: one warp per row, 16384 warps total. Finest block grain:
// 8192 blocks x 64 threads (2 warps/block) for best tail-wave packing.
#define BLOCK_THREADS 64
#define GRID_BLOCKS   (BATCH / (BLOCK_THREADS / 32))   // 8192

__global__ __launch_bounds__(BLOCK_THREADS) void mean_agg_kernel(
    const float4* __restrict__ emb,      // [N_NODES, 32] as float4
    const int* __restrict__ neigh,       // [BATCH, NUM_SAMPLE], int32
    float4* __restrict__ out)            // [BATCH, 32] as float4
{
    const int warp_id = (blockIdx.x * BLOCK_THREADS + threadIdx.x) >> 5;
    const int lane    = threadIdx.x & 31;

    // Lane l (< 25) holds sample l's neighbor index for this row.
    const int* nb = neigh + warp_id * NUM_SAMPLE;
    int my_idx = (lane < NUM_SAMPLE) ? nb[lane] : 0;

    float4 acc = make_float4(0.f, 0.f, 0.f, 0.f);

    #pragma unroll
    for (int s = 0; s < NUM_SAMPLE; ++s) {
        int id = __shfl_sync(0xffffffffu, my_idx, s);
        float4 v = __ldg(&emb[(unsigned)id * VEC_PER_ROW + lane]);
        acc.x += v.x;
        acc.y += v.y;
        acc.z += v.z;
        acc.w += v.w;
    }

    const float inv = 1.0f / (float)NUM_SAMPLE;   // 0.04
    acc.x *= inv; acc.y *= inv; acc.z *= inv; acc.w *= inv;

    out[(unsigned)warp_id * VEC_PER_ROW + lane] = acc;
}

extern "C" void kernel_launch(void* const* d_in, const int* in_sizes, int n_in,
                              void* d_out, int out_size)
{
    const float4* emb   = (const float4*)d_in[0];
    const int*    neigh = (const int*)d_in[1];
    float4*       out   = (float4*)d_out;

    mean_agg_kernel<<<GRID_BLOCKS, BLOCK_THREADS>>>(emb, neigh, out);
}

// round 12
// speedup vs baseline: 1.2769x; 1.0096x over previous
#include <cuda_runtime.h>
#include <cstdint>

#define N_NODES    100000
#define EMB_DIM    128
#define BATCH      16384
#define NUM_SAMPLE 25

#define VEC_PER_ROW (EMB_DIM / 4)   // 32 float4 per row

// Grain-trend endpoint: one CTA == one warp == one row. 16384 blocks x 32
// threads; finest scheduling quantum for tail-wave packing.
#define BLOCK_THREADS 32
#define GRID_BLOCKS   BATCH   // 16384

__global__ __launch_bounds__(BLOCK_THREADS) void mean_agg_kernel(
    const float4* __restrict__ emb,      // [N_NODES, 32] as float4
    const int* __restrict__ neigh,       // [BATCH, NUM_SAMPLE], int32
    float4* __restrict__ out)            // [BATCH, 32] as float4
{
    const int row  = blockIdx.x;
    const int lane = threadIdx.x;        // 0..31

    // Lane l (< 25) holds sample l's neighbor index for this row.
    const int* nb = neigh + row * NUM_SAMPLE;
    int my_idx = (lane < NUM_SAMPLE) ? nb[lane] : 0;

    float4 acc = make_float4(0.f, 0.f, 0.f, 0.f);

    #pragma unroll
    for (int s = 0; s < NUM_SAMPLE; ++s) {
        int id = __shfl_sync(0xffffffffu, my_idx, s);
        float4 v = __ldg(&emb[(unsigned)id * VEC_PER_ROW + lane]);
        acc.x += v.x;
        acc.y += v.y;
        acc.z += v.z;
        acc.w += v.w;
    }

    const float inv = 1.0f / (float)NUM_SAMPLE;   // 0.04
    acc.x *= inv; acc.y *= inv; acc.z *= inv; acc.w *= inv;

    out[(unsigned)row * VEC_PER_ROW + lane] = acc;
}

extern "C" void kernel_launch(void* const* d_in, const int* in_sizes, int n_in,
                              void* d_out, int out_size)
{
    const float4* emb   = (const float4*)d_in[0];
    const int*    neigh = (const int*)d_in[1];
    float4*       out   = (float4*)d_out;

    mean_agg_kernel<<<GRID_BLOCKS, BLOCK_THREADS>>>(emb, neigh, out);
}